// round 1
// baseline (speedup 1.0000x reference)
#include <cuda_runtime.h>

#define B_ 64
#define T_ 256
#define D_ 768
#define NH_ 12
#define C_ 7
#define DH_ 64

// Scratch (device globals — no allocation allowed)
__device__ float g_q[B_ * T_ * D_];
__device__ float g_k[B_ * T_ * D_];
__device__ float g_v[B_ * T_ * D_];
__device__ float g_ctx[B_ * T_ * D_];
__device__ float g_c[B_ * T_ * D_];
__device__ float g_all[B_ * T_ * C_];

// ---------------------------------------------------------------------------
// SGEMM with bias: C[M,N] = A[M,K] @ W[K,N] + bias[N]
// 128x128 tile, BK=8, 256 threads, 8x8 per thread.
// ---------------------------------------------------------------------------
#define BM 128
#define BN 128
#define BK 8
#define TM 8
#define TN 8

__global__ __launch_bounds__(256) void sgemm_bias(
    const float* __restrict__ A, const float* __restrict__ W,
    const float* __restrict__ bias, float* __restrict__ Cout,
    int M, int N, int K)
{
    __shared__ float As[BK][BM];
    __shared__ float Bs[BK][BN];

    const int tid = threadIdx.x;
    const int bx = blockIdx.x;   // N tile
    const int by = blockIdx.y;   // M tile

    const float* Ablk = A + (size_t)by * BM * K;
    const float* Wblk = W + (size_t)bx * BN;

    const int aRow = tid >> 1;          // 0..127
    const int aCol = (tid & 1) * 4;     // 0 or 4
    const int bRow = tid >> 5;          // 0..7
    const int bCol = (tid & 31) * 4;    // 0..124

    const int tx = tid & 15;
    const int ty = tid >> 4;

    float acc[TM][TN] = {};

    for (int k0 = 0; k0 < K; k0 += BK) {
        float4 av = *(const float4*)(Ablk + (size_t)aRow * K + k0 + aCol);
        As[aCol + 0][aRow] = av.x;
        As[aCol + 1][aRow] = av.y;
        As[aCol + 2][aRow] = av.z;
        As[aCol + 3][aRow] = av.w;
        float4 bv = *(const float4*)(Wblk + (size_t)(k0 + bRow) * N + bCol);
        *(float4*)(&Bs[bRow][bCol]) = bv;
        __syncthreads();

        #pragma unroll
        for (int k = 0; k < BK; k++) {
            float af[TM], bf[TN];
            #pragma unroll
            for (int i = 0; i < TM; i++) af[i] = As[k][ty * TM + i];
            #pragma unroll
            for (int j = 0; j < TN; j++) bf[j] = Bs[k][tx * TN + j];
            #pragma unroll
            for (int i = 0; i < TM; i++)
                #pragma unroll
                for (int j = 0; j < TN; j++)
                    acc[i][j] = fmaf(af[i], bf[j], acc[i][j]);
        }
        __syncthreads();
    }

    #pragma unroll
    for (int i = 0; i < TM; i++) {
        int row = by * BM + ty * TM + i;
        #pragma unroll
        for (int j = 0; j < TN; j += 4) {
            int col = bx * BN + tx * TN + j;
            float4 o;
            o.x = acc[i][j + 0] + bias[col + 0];
            o.y = acc[i][j + 1] + bias[col + 1];
            o.z = acc[i][j + 2] + bias[col + 2];
            o.w = acc[i][j + 3] + bias[col + 3];
            *(float4*)(Cout + (size_t)row * N + col) = o;
        }
    }
}

// ---------------------------------------------------------------------------
// Attention: one block per (head, batch); one thread per query.
// Keys valid for query q: k < min(q, num_turns[b]). Online softmax.
// ---------------------------------------------------------------------------
__global__ __launch_bounds__(256) void attn_kernel(const int* __restrict__ num_turns)
{
    const int h = blockIdx.x;
    const int b = blockIdx.y;
    const int q = threadIdx.x;

    __shared__ float Ks[64][64];
    __shared__ float Vs[64][64];

    const int nt = num_turns[b];
    const int limit = (q < nt) ? q : nt;          // number of valid keys
    const int maxkeys = (T_ - 1 < nt) ? (T_ - 1) : nt;  // block-wide max
    const int nchunks = (maxkeys + 63) >> 6;

    const float* qptr = g_q + ((size_t)(b * T_ + q)) * D_ + h * DH_;
    float qr[64];
    #pragma unroll
    for (int d = 0; d < 64; d += 4) {
        float4 v = *(const float4*)(qptr + d);
        qr[d] = v.x; qr[d + 1] = v.y; qr[d + 2] = v.z; qr[d + 3] = v.w;
    }

    float m = -1e30f, l = 0.f;
    float acc[64] = {};
    const float scale = 0.125f;  // 1/sqrt(64)

    for (int ch = 0; ch < nchunks; ch++) {
        const int kbase = ch * 64;
        {
            int r  = threadIdx.x >> 2;        // key within chunk, 0..63
            int c0 = (threadIdx.x & 3) * 16;  // 0,16,32,48
            const float* kp = g_k + ((size_t)(b * T_ + kbase + r)) * D_ + h * DH_ + c0;
            const float* vp = g_v + ((size_t)(b * T_ + kbase + r)) * D_ + h * DH_ + c0;
            #pragma unroll
            for (int j = 0; j < 16; j += 4) {
                *(float4*)(&Ks[r][c0 + j]) = *(const float4*)(kp + j);
                *(float4*)(&Vs[r][c0 + j]) = *(const float4*)(vp + j);
            }
        }
        __syncthreads();

        const int kend = (64 < limit - kbase) ? 64 : (limit - kbase);
        for (int kk = 0; kk < kend; kk++) {
            float s = 0.f;
            #pragma unroll
            for (int d = 0; d < 64; d++) s = fmaf(qr[d], Ks[kk][d], s);
            s *= scale;
            if (s > m) {
                float corr = __expf(m - s);
                m = s;
                l = l * corr + 1.f;
                #pragma unroll
                for (int d = 0; d < 64; d++) acc[d] = acc[d] * corr + Vs[kk][d];
            } else {
                float p = __expf(s - m);
                l += p;
                #pragma unroll
                for (int d = 0; d < 64; d++) acc[d] = fmaf(p, Vs[kk][d], acc[d]);
            }
        }
        __syncthreads();
    }

    float* op = g_ctx + ((size_t)(b * T_ + q)) * D_ + h * DH_;
    if (limit > 0) {
        float invl = 1.f / l;
        #pragma unroll
        for (int d = 0; d < 64; d += 4) {
            float4 o;
            o.x = acc[d] * invl; o.y = acc[d + 1] * invl;
            o.z = acc[d + 2] * invl; o.w = acc[d + 3] * invl;
            *(float4*)(op + d) = o;
        }
    } else {
        float4 z = {0.f, 0.f, 0.f, 0.f};
        #pragma unroll
        for (int d = 0; d < 64; d += 4) *(float4*)(op + d) = z;
    }
}

// ---------------------------------------------------------------------------
// Classifier: all_logits[b,t,:] = H[b,t,:]@Wc[:D] + (t>0 ? c[b,t,:]@Wc[D:] : 0) + bc
// 8 rows per block; Wc resident in smem.
// ---------------------------------------------------------------------------
#define CL_ROWS 8

__global__ __launch_bounds__(256) void classifier_kernel(
    const float* __restrict__ H, const float* __restrict__ Wc,
    const float* __restrict__ bc)
{
    __shared__ float sWc[2 * D_ * C_];   // 10752 floats = 43008 B
    __shared__ float sred[8 * C_];

    const int tid = threadIdx.x;
    for (int i = tid; i < 2 * D_ * C_; i += 256) sWc[i] = Wc[i];
    __syncthreads();

    const int row0 = blockIdx.x * CL_ROWS;
    for (int r = 0; r < CL_ROWS; r++) {
        const int row = row0 + r;
        const int t = row & (T_ - 1);    // row = b*T + t, T=256
        float facc[C_] = {};
        for (int d = tid; d < D_; d += 256) {
            float hv = H[(size_t)row * D_ + d];
            #pragma unroll
            for (int c = 0; c < C_; c++) facc[c] = fmaf(hv, sWc[d * C_ + c], facc[c]);
            if (t > 0) {
                float cv = g_c[(size_t)row * D_ + d];
                #pragma unroll
                for (int c = 0; c < C_; c++) facc[c] = fmaf(cv, sWc[(D_ + d) * C_ + c], facc[c]);
            }
        }
        #pragma unroll
        for (int c = 0; c < C_; c++)
            #pragma unroll
            for (int off = 16; off; off >>= 1)
                facc[c] += __shfl_down_sync(0xffffffff, facc[c], off);
        if ((tid & 31) == 0) {
            int w = tid >> 5;
            #pragma unroll
            for (int c = 0; c < C_; c++) sred[w * C_ + c] = facc[c];
        }
        __syncthreads();
        if (tid < C_) {
            float s = bc[tid];
            #pragma unroll
            for (int w = 0; w < 8; w++) s += sred[w * C_ + tid];
            g_all[(size_t)row * C_ + tid] = s;
        }
        __syncthreads();
    }
}

// ---------------------------------------------------------------------------
// Finalize: write outputs into d_out per its size.
// Layout (expected): all_logits [B*T*C] then final_logits [B*C].
// ---------------------------------------------------------------------------
__global__ void finalize_kernel(const int* __restrict__ nt, float* __restrict__ out,
                                int out_size)
{
    const int ALL = B_ * T_ * C_;
    const int FIN = B_ * C_;
    int i = blockIdx.x * blockDim.x + threadIdx.x;
    if (out_size >= ALL + FIN) {
        if (i < ALL) out[i] = g_all[i];
        if (i < FIN) {
            int b = i / C_, c = i - b * C_;
            int t = nt[b] - 1;
            out[ALL + i] = g_all[((size_t)(b * T_ + t)) * C_ + c];
        }
    } else if (out_size >= ALL) {
        if (i < ALL) out[i] = g_all[i];
    } else {
        if (i < FIN) {
            int b = i / C_, c = i - b * C_;
            int t = nt[b] - 1;
            out[i] = g_all[((size_t)(b * T_ + t)) * C_ + c];
        }
    }
}

// ---------------------------------------------------------------------------
extern "C" void kernel_launch(void* const* d_in, const int* in_sizes, int n_in,
                              void* d_out, int out_size)
{
    const float* H  = (const float*)d_in[0];
    const float* Wq = (const float*)d_in[1];
    const float* bq = (const float*)d_in[2];
    const float* Wk = (const float*)d_in[3];
    const float* bk = (const float*)d_in[4];
    const float* Wv = (const float*)d_in[5];
    const float* bv = (const float*)d_in[6];
    const float* Wo = (const float*)d_in[7];
    const float* bo = (const float*)d_in[8];
    const float* Wc = (const float*)d_in[9];
    const float* bc = (const float*)d_in[10];
    const int*   nt = (const int*)d_in[11];
    float* out = (float*)d_out;

    float *pq, *pk, *pv, *pctx, *pc;
    cudaGetSymbolAddress((void**)&pq,   g_q);
    cudaGetSymbolAddress((void**)&pk,   g_k);
    cudaGetSymbolAddress((void**)&pv,   g_v);
    cudaGetSymbolAddress((void**)&pctx, g_ctx);
    cudaGetSymbolAddress((void**)&pc,   g_c);

    const int M = B_ * T_;
    dim3 ggrid(D_ / BN, M / BM);  // (6, 128)

    sgemm_bias<<<ggrid, 256>>>(H, Wq, bq, pq, M, D_, D_);
    sgemm_bias<<<ggrid, 256>>>(H, Wk, bk, pk, M, D_, D_);
    sgemm_bias<<<ggrid, 256>>>(H, Wv, bv, pv, M, D_, D_);

    attn_kernel<<<dim3(NH_, B_), 256>>>(nt);

    sgemm_bias<<<ggrid, 256>>>(pctx, Wo, bo, pc, M, D_, D_);

    classifier_kernel<<<M / CL_ROWS, 256>>>(H, Wc, bc);

    const int ALL = B_ * T_ * C_;
    finalize_kernel<<<(ALL + 255) / 256, 256>>>(nt, out, out_size);
}

// round 2
// speedup vs baseline: 2.1557x; 2.1557x over previous
#include <cuda_runtime.h>

#define B_ 64
#define T_ 256
#define D_ 768
#define NH_ 12
#define C_ 7
#define DH_ 64

// Scratch (device globals — no allocation allowed)
__device__ float g_q[B_ * T_ * D_];
__device__ float g_k[B_ * T_ * D_];
__device__ float g_v[B_ * T_ * D_];
__device__ float g_ctx[B_ * T_ * D_];
__device__ float g_c[B_ * T_ * D_];
__device__ float g_all[B_ * T_ * C_];

// ---------------------------------------------------------------------------
// TF32 tensor-core GEMM with bias: C[M,N] = A[M,K] @ W[K,N] + bias[N]
// 128x128 tile, BK=16, 256 threads (8 warps, 4x2), warp tile 32x64.
// mma.sync.m16n8k8 tf32. gridDim.z selects among up to 3 (W,b,out) triples
// so QKV runs as ONE launch.
// ---------------------------------------------------------------------------
#define GBM 128
#define GBN 128
#define GBK 16

__device__ __forceinline__ unsigned f2tf32(float x) {
    unsigned r;
    asm("cvt.rna.tf32.f32 %0, %1;" : "=r"(r) : "f"(x));
    return r;
}

__device__ __forceinline__ void mma_tf32(float c[4], const unsigned a[4], const unsigned b[2]) {
    asm volatile(
        "mma.sync.aligned.m16n8k8.row.col.f32.tf32.tf32.f32 "
        "{%0,%1,%2,%3},{%4,%5,%6,%7},{%8,%9},{%0,%1,%2,%3};"
        : "+f"(c[0]), "+f"(c[1]), "+f"(c[2]), "+f"(c[3])
        : "r"(a[0]), "r"(a[1]), "r"(a[2]), "r"(a[3]), "r"(b[0]), "r"(b[1]));
}

__global__ __launch_bounds__(256, 2) void tf32_gemm_bias(
    const float* __restrict__ A,
    const float* __restrict__ W0, const float* __restrict__ b0, float* __restrict__ O0,
    const float* __restrict__ W1, const float* __restrict__ b1, float* __restrict__ O1,
    const float* __restrict__ W2, const float* __restrict__ b2, float* __restrict__ O2,
    int M, int N, int K)
{
    const float* W    = (blockIdx.z == 0) ? W0 : (blockIdx.z == 1) ? W1 : W2;
    const float* bias = (blockIdx.z == 0) ? b0 : (blockIdx.z == 1) ? b1 : b2;
    float*       Cout = (blockIdx.z == 0) ? O0 : (blockIdx.z == 1) ? O1 : O2;

    // As[m][k] padded to 20 (bank-conflict-free frag loads: 4*gid+tig pattern)
    // Bs[k][n] padded to 136 (8*tig+gid pattern)
    __shared__ float As[GBM][20];
    __shared__ float Bs[GBK][136];

    const int tid = threadIdx.x;
    const int bx = blockIdx.x;   // N tile
    const int by = blockIdx.y;   // M tile

    const int warp = tid >> 5;
    const int lane = tid & 31;
    const int gid = lane >> 2;   // 0..7
    const int tig = lane & 3;    // 0..3
    const int m0 = (warp & 3) * 32;   // warp m offset in tile
    const int n0 = (warp >> 2) * 64;  // warp n offset in tile

    const float* Ablk = A + (size_t)by * GBM * K;
    const float* Wblk = W + (size_t)bx * GBN;

    // A tile load map: row=tid>>1 (0..127), kchunk=(tid&1)*8
    const int aRow = tid >> 1;
    const int aCol = (tid & 1) * 8;
    // B tile load map: row=tid>>4 (0..15), col=(tid&15)*8
    const int bRow = tid >> 4;
    const int bCol = (tid & 15) * 8;

    float acc[2][8][4] = {};   // [mtile][ntile][frag]

    for (int k0 = 0; k0 < K; k0 += GBK) {
        // Load A 128x16
        {
            float4 v0 = *(const float4*)(Ablk + (size_t)aRow * K + k0 + aCol);
            float4 v1 = *(const float4*)(Ablk + (size_t)aRow * K + k0 + aCol + 4);
            As[aRow][aCol + 0] = __uint_as_float(f2tf32(v0.x));
            As[aRow][aCol + 1] = __uint_as_float(f2tf32(v0.y));
            As[aRow][aCol + 2] = __uint_as_float(f2tf32(v0.z));
            As[aRow][aCol + 3] = __uint_as_float(f2tf32(v0.w));
            As[aRow][aCol + 4] = __uint_as_float(f2tf32(v1.x));
            As[aRow][aCol + 5] = __uint_as_float(f2tf32(v1.y));
            As[aRow][aCol + 6] = __uint_as_float(f2tf32(v1.z));
            As[aRow][aCol + 7] = __uint_as_float(f2tf32(v1.w));
        }
        // Load B 16x128
        {
            const float* src = Wblk + (size_t)(k0 + bRow) * N + bCol;
            float4 v0 = *(const float4*)(src);
            float4 v1 = *(const float4*)(src + 4);
            Bs[bRow][bCol + 0] = __uint_as_float(f2tf32(v0.x));
            Bs[bRow][bCol + 1] = __uint_as_float(f2tf32(v0.y));
            Bs[bRow][bCol + 2] = __uint_as_float(f2tf32(v0.z));
            Bs[bRow][bCol + 3] = __uint_as_float(f2tf32(v0.w));
            Bs[bRow][bCol + 4] = __uint_as_float(f2tf32(v1.x));
            Bs[bRow][bCol + 5] = __uint_as_float(f2tf32(v1.y));
            Bs[bRow][bCol + 6] = __uint_as_float(f2tf32(v1.z));
            Bs[bRow][bCol + 7] = __uint_as_float(f2tf32(v1.w));
        }
        __syncthreads();

        #pragma unroll
        for (int kk = 0; kk < GBK; kk += 8) {
            unsigned a[2][4], b[8][2];
            #pragma unroll
            for (int mt = 0; mt < 2; mt++) {
                int mr = m0 + mt * 16 + gid;
                a[mt][0] = __float_as_uint(As[mr    ][kk + tig    ]);
                a[mt][1] = __float_as_uint(As[mr + 8][kk + tig    ]);
                a[mt][2] = __float_as_uint(As[mr    ][kk + tig + 4]);
                a[mt][3] = __float_as_uint(As[mr + 8][kk + tig + 4]);
            }
            #pragma unroll
            for (int nt = 0; nt < 8; nt++) {
                int nc = n0 + nt * 8 + gid;
                b[nt][0] = __float_as_uint(Bs[kk + tig    ][nc]);
                b[nt][1] = __float_as_uint(Bs[kk + tig + 4][nc]);
            }
            #pragma unroll
            for (int mt = 0; mt < 2; mt++)
                #pragma unroll
                for (int nt = 0; nt < 8; nt++)
                    mma_tf32(acc[mt][nt], a[mt], b[nt]);
        }
        __syncthreads();
    }

    // Epilogue: c0 at (gid, tig*2), c1 (+1 col), c2/c3 at row+8
    #pragma unroll
    for (int mt = 0; mt < 2; mt++) {
        #pragma unroll
        for (int nt = 0; nt < 8; nt++) {
            int row = by * GBM + m0 + mt * 16 + gid;
            int col = bx * GBN + n0 + nt * 8 + tig * 2;
            float bx0 = bias[col], bx1 = bias[col + 1];
            float2 o0 = {acc[mt][nt][0] + bx0, acc[mt][nt][1] + bx1};
            float2 o1 = {acc[mt][nt][2] + bx0, acc[mt][nt][3] + bx1};
            *(float2*)(Cout + (size_t)row * N + col) = o0;
            *(float2*)(Cout + (size_t)(row + 8) * N + col) = o1;
        }
    }
}

// ---------------------------------------------------------------------------
// Attention: one block per (head, batch); one thread per query.
// Keys valid for query q: k < min(q, num_turns[b]). Online softmax.
// Dot product split into 4 accumulators to break the dependency chain.
// ---------------------------------------------------------------------------
__global__ __launch_bounds__(256) void attn_kernel(const int* __restrict__ num_turns)
{
    const int h = blockIdx.x;
    const int b = blockIdx.y;
    const int q = threadIdx.x;

    __shared__ float Ks[64][64];
    __shared__ float Vs[64][64];

    const int nt = num_turns[b];
    const int limit = (q < nt) ? q : nt;
    const int maxkeys = (T_ - 1 < nt) ? (T_ - 1) : nt;
    const int nchunks = (maxkeys + 63) >> 6;

    const float* qptr = g_q + ((size_t)(b * T_ + q)) * D_ + h * DH_;
    float qr[64];
    #pragma unroll
    for (int d = 0; d < 64; d += 4) {
        float4 v = *(const float4*)(qptr + d);
        qr[d] = v.x; qr[d + 1] = v.y; qr[d + 2] = v.z; qr[d + 3] = v.w;
    }

    float m = -1e30f, l = 0.f;
    float acc[64] = {};
    const float scale = 0.125f;

    for (int ch = 0; ch < nchunks; ch++) {
        const int kbase = ch * 64;
        {
            int r  = threadIdx.x >> 2;
            int c0 = (threadIdx.x & 3) * 16;
            const float* kp = g_k + ((size_t)(b * T_ + kbase + r)) * D_ + h * DH_ + c0;
            const float* vp = g_v + ((size_t)(b * T_ + kbase + r)) * D_ + h * DH_ + c0;
            #pragma unroll
            for (int j = 0; j < 16; j += 4) {
                *(float4*)(&Ks[r][c0 + j]) = *(const float4*)(kp + j);
                *(float4*)(&Vs[r][c0 + j]) = *(const float4*)(vp + j);
            }
        }
        __syncthreads();

        const int kend = (64 < limit - kbase) ? 64 : (limit - kbase);
        for (int kk = 0; kk < kend; kk++) {
            float s0 = 0.f, s1 = 0.f, s2 = 0.f, s3 = 0.f;
            #pragma unroll
            for (int d = 0; d < 64; d += 4) {
                s0 = fmaf(qr[d    ], Ks[kk][d    ], s0);
                s1 = fmaf(qr[d + 1], Ks[kk][d + 1], s1);
                s2 = fmaf(qr[d + 2], Ks[kk][d + 2], s2);
                s3 = fmaf(qr[d + 3], Ks[kk][d + 3], s3);
            }
            float s = ((s0 + s1) + (s2 + s3)) * scale;
            if (s > m) {
                float corr = __expf(m - s);
                m = s;
                l = l * corr + 1.f;
                #pragma unroll
                for (int d = 0; d < 64; d++) acc[d] = acc[d] * corr + Vs[kk][d];
            } else {
                float p = __expf(s - m);
                l += p;
                #pragma unroll
                for (int d = 0; d < 64; d++) acc[d] = fmaf(p, Vs[kk][d], acc[d]);
            }
        }
        __syncthreads();
    }

    float* op = g_ctx + ((size_t)(b * T_ + q)) * D_ + h * DH_;
    if (limit > 0) {
        float invl = 1.f / l;
        #pragma unroll
        for (int d = 0; d < 64; d += 4) {
            float4 o;
            o.x = acc[d] * invl; o.y = acc[d + 1] * invl;
            o.z = acc[d + 2] * invl; o.w = acc[d + 3] * invl;
            *(float4*)(op + d) = o;
        }
    } else {
        float4 z = {0.f, 0.f, 0.f, 0.f};
        #pragma unroll
        for (int d = 0; d < 64; d += 4) *(float4*)(op + d) = z;
    }
}

// ---------------------------------------------------------------------------
// Classifier: all_logits[b,t,:] = H[b,t,:]@Wc[:D] + (t>0 ? c[b,t,:]@Wc[D:] : 0) + bc
// ---------------------------------------------------------------------------
#define CL_ROWS 8

__global__ __launch_bounds__(256) void classifier_kernel(
    const float* __restrict__ H, const float* __restrict__ Wc,
    const float* __restrict__ bc)
{
    __shared__ float sWc[2 * D_ * C_];
    __shared__ float sred[8 * C_];

    const int tid = threadIdx.x;
    for (int i = tid; i < 2 * D_ * C_; i += 256) sWc[i] = Wc[i];
    __syncthreads();

    const int row0 = blockIdx.x * CL_ROWS;
    for (int r = 0; r < CL_ROWS; r++) {
        const int row = row0 + r;
        const int t = row & (T_ - 1);
        float facc[C_] = {};
        for (int d = tid; d < D_; d += 256) {
            float hv = H[(size_t)row * D_ + d];
            #pragma unroll
            for (int c = 0; c < C_; c++) facc[c] = fmaf(hv, sWc[d * C_ + c], facc[c]);
            if (t > 0) {
                float cv = g_c[(size_t)row * D_ + d];
                #pragma unroll
                for (int c = 0; c < C_; c++) facc[c] = fmaf(cv, sWc[(D_ + d) * C_ + c], facc[c]);
            }
        }
        #pragma unroll
        for (int c = 0; c < C_; c++)
            #pragma unroll
            for (int off = 16; off; off >>= 1)
                facc[c] += __shfl_down_sync(0xffffffff, facc[c], off);
        if ((tid & 31) == 0) {
            int w = tid >> 5;
            #pragma unroll
            for (int c = 0; c < C_; c++) sred[w * C_ + c] = facc[c];
        }
        __syncthreads();
        if (tid < C_) {
            float s = bc[tid];
            #pragma unroll
            for (int w = 0; w < 8; w++) s += sred[w * C_ + tid];
            g_all[(size_t)row * C_ + tid] = s;
        }
        __syncthreads();
    }
}

// ---------------------------------------------------------------------------
__global__ void finalize_kernel(const int* __restrict__ nt, float* __restrict__ out,
                                int out_size)
{
    const int ALL = B_ * T_ * C_;
    const int FIN = B_ * C_;
    int i = blockIdx.x * blockDim.x + threadIdx.x;
    if (out_size >= ALL + FIN) {
        if (i < ALL) out[i] = g_all[i];
        if (i < FIN) {
            int b = i / C_, c = i - b * C_;
            int t = nt[b] - 1;
            out[ALL + i] = g_all[((size_t)(b * T_ + t)) * C_ + c];
        }
    } else if (out_size >= ALL) {
        if (i < ALL) out[i] = g_all[i];
    } else {
        if (i < FIN) {
            int b = i / C_, c = i - b * C_;
            int t = nt[b] - 1;
            out[i] = g_all[((size_t)(b * T_ + t)) * C_ + c];
        }
    }
}

// ---------------------------------------------------------------------------
extern "C" void kernel_launch(void* const* d_in, const int* in_sizes, int n_in,
                              void* d_out, int out_size)
{
    const float* H  = (const float*)d_in[0];
    const float* Wq = (const float*)d_in[1];
    const float* bq = (const float*)d_in[2];
    const float* Wk = (const float*)d_in[3];
    const float* bk = (const float*)d_in[4];
    const float* Wv = (const float*)d_in[5];
    const float* bv = (const float*)d_in[6];
    const float* Wo = (const float*)d_in[7];
    const float* bo = (const float*)d_in[8];
    const float* Wc = (const float*)d_in[9];
    const float* bc = (const float*)d_in[10];
    const int*   nt = (const int*)d_in[11];
    float* out = (float*)d_out;

    float *pq, *pk, *pv, *pctx, *pc;
    cudaGetSymbolAddress((void**)&pq,   g_q);
    cudaGetSymbolAddress((void**)&pk,   g_k);
    cudaGetSymbolAddress((void**)&pv,   g_v);
    cudaGetSymbolAddress((void**)&pctx, g_ctx);
    cudaGetSymbolAddress((void**)&pc,   g_c);

    const int M = B_ * T_;

    // Fused QKV: one launch, gridDim.z = 3
    dim3 qkv_grid(D_ / GBN, M / GBM, 3);
    tf32_gemm_bias<<<qkv_grid, 256>>>(H, Wq, bq, pq, Wk, bk, pk, Wv, bv, pv, M, D_, D_);

    attn_kernel<<<dim3(NH_, B_), 256>>>(nt);

    dim3 o_grid(D_ / GBN, M / GBM, 1);
    tf32_gemm_bias<<<o_grid, 256>>>(pctx, Wo, bo, pc, Wo, bo, pc, Wo, bo, pc, M, D_, D_);

    classifier_kernel<<<M / CL_ROWS, 256>>>(H, Wc, bc);

    const int ALL = B_ * T_ * C_;
    finalize_kernel<<<(ALL + 255) / 256, 256>>>(nt, out, out_size);
}

// round 3
// speedup vs baseline: 2.8494x; 1.3218x over previous
#include <cuda_runtime.h>

#define B_ 64
#define T_ 256
#define D_ 768
#define NH_ 12
#define C_ 7
#define DH_ 64

// Scratch (device globals — no allocation allowed)
__device__ float g_q[B_ * T_ * D_];
__device__ float g_k[B_ * T_ * D_];
__device__ float g_v[B_ * T_ * D_];
__device__ float g_ctx[B_ * T_ * D_];
__device__ float g_c[B_ * T_ * D_];
__device__ float g_all[B_ * T_ * C_];

// ---------------------------------------------------------------------------
// TF32 tensor-core GEMM with bias: C[M,N] = A[M,K] @ W[K,N] + bias[N]
// 128x128 tile, BK=32, 256 threads (8 warps, 4x2), warp tile 32x64.
// 2-stage cp.async pipeline; raw fp32 bits fed to tf32 MMA (hw truncation).
// gridDim.z selects among up to 3 (W,b,out) triples so QKV is ONE launch.
// ---------------------------------------------------------------------------
#define GBM 128
#define GBN 128
#define GBK 32
#define A_STRIDE 36        // 128 rows x 36 floats (16B-aligned rows, pad 4)
#define B_STRIDE 136       // 32 rows x 136 floats (16B-aligned rows, pad 8)
#define STAGE_FLOATS (GBM * A_STRIDE + GBK * B_STRIDE)   // 4608 + 4352 = 8960
#define GEMM_SMEM_BYTES (2 * STAGE_FLOATS * 4)            // 71680

__device__ __forceinline__ void cp_async16(float* dst, const float* src) {
    unsigned saddr = (unsigned)__cvta_generic_to_shared(dst);
    asm volatile("cp.async.cg.shared.global [%0], [%1], 16;" :: "r"(saddr), "l"(src) : "memory");
}
__device__ __forceinline__ void cp_commit() {
    asm volatile("cp.async.commit_group;" ::: "memory");
}
__device__ __forceinline__ void cp_wait1() {
    asm volatile("cp.async.wait_group 1;" ::: "memory");
}

__device__ __forceinline__ void mma_tf32(float c[4], const unsigned a[4], const unsigned b[2]) {
    asm volatile(
        "mma.sync.aligned.m16n8k8.row.col.f32.tf32.tf32.f32 "
        "{%0,%1,%2,%3},{%4,%5,%6,%7},{%8,%9},{%0,%1,%2,%3};"
        : "+f"(c[0]), "+f"(c[1]), "+f"(c[2]), "+f"(c[3])
        : "r"(a[0]), "r"(a[1]), "r"(a[2]), "r"(a[3]), "r"(b[0]), "r"(b[1]));
}

__global__ __launch_bounds__(256, 2) void tf32_gemm_bias(
    const float* __restrict__ A,
    const float* __restrict__ W0, const float* __restrict__ b0, float* __restrict__ O0,
    const float* __restrict__ W1, const float* __restrict__ b1, float* __restrict__ O1,
    const float* __restrict__ W2, const float* __restrict__ b2, float* __restrict__ O2,
    int M, int N, int K)
{
    const float* W    = (blockIdx.z == 0) ? W0 : (blockIdx.z == 1) ? W1 : W2;
    const float* bias = (blockIdx.z == 0) ? b0 : (blockIdx.z == 1) ? b1 : b2;
    float*       Cout = (blockIdx.z == 0) ? O0 : (blockIdx.z == 1) ? O1 : O2;

    extern __shared__ float smem[];

    const int tid = threadIdx.x;
    const int bx = blockIdx.x;   // N tile
    const int by = blockIdx.y;   // M tile

    const int warp = tid >> 5;
    const int lane = tid & 31;
    const int gid = lane >> 2;   // 0..7
    const int tig = lane & 3;    // 0..3
    const int m0 = (warp & 3) * 32;   // warp m offset
    const int n0 = (warp >> 2) * 64;  // warp n offset

    const float* Ablk = A + (size_t)by * GBM * K;
    const float* Wblk = W + (size_t)bx * GBN;

    // cp.async maps
    const int arow = tid >> 3;          // 0..31 (+32 steps)
    const int acol = (tid & 7) * 4;     // 0..28
    const int brow = tid >> 5;          // 0..7 (+8 steps)
    const int bcol = (tid & 31) * 4;    // 0..124

    float acc[2][8][4] = {};

    const int KT = K / GBK;   // 24

    // prologue: stage 0
    {
        float* sA = smem;
        float* sB = smem + GBM * A_STRIDE;
        #pragma unroll
        for (int i = 0; i < 4; i++)
            cp_async16(sA + (arow + i * 32) * A_STRIDE + acol,
                       Ablk + (size_t)(arow + i * 32) * K + acol);
        #pragma unroll
        for (int i = 0; i < 4; i++)
            cp_async16(sB + (brow + i * 8) * B_STRIDE + bcol,
                       Wblk + (size_t)(brow + i * 8) * N + bcol);
        cp_commit();
    }

    for (int kt = 0; kt < KT; kt++) {
        // issue next stage
        if (kt + 1 < KT) {
            const int k0 = (kt + 1) * GBK;
            float* sA = smem + ((kt + 1) & 1) * STAGE_FLOATS;
            float* sB = sA + GBM * A_STRIDE;
            #pragma unroll
            for (int i = 0; i < 4; i++)
                cp_async16(sA + (arow + i * 32) * A_STRIDE + acol,
                           Ablk + (size_t)(arow + i * 32) * K + k0 + acol);
            #pragma unroll
            for (int i = 0; i < 4; i++)
                cp_async16(sB + (brow + i * 8) * B_STRIDE + bcol,
                           Wblk + (size_t)(k0 + brow + i * 8) * N + bcol);
        }
        cp_commit();
        cp_wait1();            // current stage (group kt) complete
        __syncthreads();

        const float* sA = smem + (kt & 1) * STAGE_FLOATS;
        const float* sB = sA + GBM * A_STRIDE;

        #pragma unroll
        for (int kk = 0; kk < GBK; kk += 8) {
            unsigned a[2][4], b[8][2];
            #pragma unroll
            for (int mt = 0; mt < 2; mt++) {
                int mr = m0 + mt * 16 + gid;
                a[mt][0] = __float_as_uint(sA[mr * A_STRIDE + kk + tig]);
                a[mt][1] = __float_as_uint(sA[(mr + 8) * A_STRIDE + kk + tig]);
                a[mt][2] = __float_as_uint(sA[mr * A_STRIDE + kk + tig + 4]);
                a[mt][3] = __float_as_uint(sA[(mr + 8) * A_STRIDE + kk + tig + 4]);
            }
            #pragma unroll
            for (int nt = 0; nt < 8; nt++) {
                int nc = n0 + nt * 8 + gid;
                b[nt][0] = __float_as_uint(sB[(kk + tig) * B_STRIDE + nc]);
                b[nt][1] = __float_as_uint(sB[(kk + tig + 4) * B_STRIDE + nc]);
            }
            #pragma unroll
            for (int mt = 0; mt < 2; mt++)
                #pragma unroll
                for (int nt = 0; nt < 8; nt++)
                    mma_tf32(acc[mt][nt], a[mt], b[nt]);
        }
        __syncthreads();       // done reading before stage gets overwritten
    }

    #pragma unroll
    for (int mt = 0; mt < 2; mt++) {
        #pragma unroll
        for (int nt = 0; nt < 8; nt++) {
            int row = by * GBM + m0 + mt * 16 + gid;
            int col = bx * GBN + n0 + nt * 8 + tig * 2;
            float bx0 = bias[col], bx1 = bias[col + 1];
            float2 o0 = {acc[mt][nt][0] + bx0, acc[mt][nt][1] + bx1};
            float2 o1 = {acc[mt][nt][2] + bx0, acc[mt][nt][3] + bx1};
            *(float2*)(Cout + (size_t)row * N + col) = o0;
            *(float2*)(Cout + (size_t)(row + 8) * N + col) = o1;
        }
    }
}

// ---------------------------------------------------------------------------
// Attention: one block per (head, batch); one thread per query.
// Keys valid for query q: k < min(q, num_turns[b]). Online softmax.
// ---------------------------------------------------------------------------
__global__ __launch_bounds__(256) void attn_kernel(const int* __restrict__ num_turns)
{
    const int h = blockIdx.x;
    const int b = blockIdx.y;
    const int q = threadIdx.x;

    __shared__ float Ks[64][64];
    __shared__ float Vs[64][64];

    const int nt = num_turns[b];
    const int limit = (q < nt) ? q : nt;
    const int maxkeys = (T_ - 1 < nt) ? (T_ - 1) : nt;
    const int nchunks = (maxkeys + 63) >> 6;

    const float* qptr = g_q + ((size_t)(b * T_ + q)) * D_ + h * DH_;
    float qr[64];
    #pragma unroll
    for (int d = 0; d < 64; d += 4) {
        float4 v = *(const float4*)(qptr + d);
        qr[d] = v.x; qr[d + 1] = v.y; qr[d + 2] = v.z; qr[d + 3] = v.w;
    }

    float m = -1e30f, l = 0.f;
    float acc[64] = {};
    const float scale = 0.125f;

    for (int ch = 0; ch < nchunks; ch++) {
        const int kbase = ch * 64;
        {
            int r  = threadIdx.x >> 2;
            int c0 = (threadIdx.x & 3) * 16;
            const float* kp = g_k + ((size_t)(b * T_ + kbase + r)) * D_ + h * DH_ + c0;
            const float* vp = g_v + ((size_t)(b * T_ + kbase + r)) * D_ + h * DH_ + c0;
            #pragma unroll
            for (int j = 0; j < 16; j += 4) {
                *(float4*)(&Ks[r][c0 + j]) = *(const float4*)(kp + j);
                *(float4*)(&Vs[r][c0 + j]) = *(const float4*)(vp + j);
            }
        }
        __syncthreads();

        const int kend = (64 < limit - kbase) ? 64 : (limit - kbase);
        for (int kk = 0; kk < kend; kk++) {
            const float4* kr = (const float4*)(&Ks[kk][0]);
            float s0 = 0.f, s1 = 0.f, s2 = 0.f, s3 = 0.f;
            #pragma unroll
            for (int i = 0; i < 16; i++) {
                float4 kv = kr[i];
                s0 = fmaf(qr[4 * i    ], kv.x, s0);
                s1 = fmaf(qr[4 * i + 1], kv.y, s1);
                s2 = fmaf(qr[4 * i + 2], kv.z, s2);
                s3 = fmaf(qr[4 * i + 3], kv.w, s3);
            }
            float s = ((s0 + s1) + (s2 + s3)) * scale;
            const float4* vr = (const float4*)(&Vs[kk][0]);
            if (s > m) {
                float corr = __expf(m - s);
                m = s;
                l = l * corr + 1.f;
                #pragma unroll
                for (int i = 0; i < 16; i++) {
                    float4 vv = vr[i];
                    acc[4 * i    ] = acc[4 * i    ] * corr + vv.x;
                    acc[4 * i + 1] = acc[4 * i + 1] * corr + vv.y;
                    acc[4 * i + 2] = acc[4 * i + 2] * corr + vv.z;
                    acc[4 * i + 3] = acc[4 * i + 3] * corr + vv.w;
                }
            } else {
                float p = __expf(s - m);
                l += p;
                #pragma unroll
                for (int i = 0; i < 16; i++) {
                    float4 vv = vr[i];
                    acc[4 * i    ] = fmaf(p, vv.x, acc[4 * i    ]);
                    acc[4 * i + 1] = fmaf(p, vv.y, acc[4 * i + 1]);
                    acc[4 * i + 2] = fmaf(p, vv.z, acc[4 * i + 2]);
                    acc[4 * i + 3] = fmaf(p, vv.w, acc[4 * i + 3]);
                }
            }
        }
        __syncthreads();
    }

    float* op = g_ctx + ((size_t)(b * T_ + q)) * D_ + h * DH_;
    if (limit > 0) {
        float invl = 1.f / l;
        #pragma unroll
        for (int d = 0; d < 64; d += 4) {
            float4 o;
            o.x = acc[d] * invl; o.y = acc[d + 1] * invl;
            o.z = acc[d + 2] * invl; o.w = acc[d + 3] * invl;
            *(float4*)(op + d) = o;
        }
    } else {
        float4 z = {0.f, 0.f, 0.f, 0.f};
        #pragma unroll
        for (int d = 0; d < 64; d += 4) *(float4*)(op + d) = z;
    }
}

// ---------------------------------------------------------------------------
// Classifier: all_logits[b,t,:] = H[b,t,:]@Wc[:D] + (t>0 ? c[b,t,:]@Wc[D:] : 0) + bc
// 192 threads; thread d4 handles float4 chunk d4 (D/4 = 192). 16 rows/block.
// ---------------------------------------------------------------------------
#define CL_ROWS 16
#define CL_THREADS 192

__global__ __launch_bounds__(CL_THREADS) void classifier_kernel(
    const float* __restrict__ H, const float* __restrict__ Wc,
    const float* __restrict__ bc)
{
    __shared__ float sWc[2 * D_ * C_];
    __shared__ float sred[6 * C_];

    const int tid = threadIdx.x;
    for (int i = tid; i < 2 * D_ * C_; i += CL_THREADS) sWc[i] = Wc[i];
    __syncthreads();

    const int d0 = tid * 4;
    const int row0 = blockIdx.x * CL_ROWS;

    for (int r = 0; r < CL_ROWS; r++) {
        const int row = row0 + r;
        const int t = row & (T_ - 1);
        float facc[C_] = {};
        {
            float4 hv = *(const float4*)(H + (size_t)row * D_ + d0);
            #pragma unroll
            for (int c = 0; c < C_; c++) {
                facc[c] = fmaf(hv.x, sWc[(d0    ) * C_ + c], facc[c]);
                facc[c] = fmaf(hv.y, sWc[(d0 + 1) * C_ + c], facc[c]);
                facc[c] = fmaf(hv.z, sWc[(d0 + 2) * C_ + c], facc[c]);
                facc[c] = fmaf(hv.w, sWc[(d0 + 3) * C_ + c], facc[c]);
            }
            if (t > 0) {
                float4 cv = *(const float4*)(g_c + (size_t)row * D_ + d0);
                #pragma unroll
                for (int c = 0; c < C_; c++) {
                    facc[c] = fmaf(cv.x, sWc[(D_ + d0    ) * C_ + c], facc[c]);
                    facc[c] = fmaf(cv.y, sWc[(D_ + d0 + 1) * C_ + c], facc[c]);
                    facc[c] = fmaf(cv.z, sWc[(D_ + d0 + 2) * C_ + c], facc[c]);
                    facc[c] = fmaf(cv.w, sWc[(D_ + d0 + 3) * C_ + c], facc[c]);
                }
            }
        }
        #pragma unroll
        for (int c = 0; c < C_; c++)
            #pragma unroll
            for (int off = 16; off; off >>= 1)
                facc[c] += __shfl_down_sync(0xffffffff, facc[c], off);
        if ((tid & 31) == 0) {
            int w = tid >> 5;
            #pragma unroll
            for (int c = 0; c < C_; c++) sred[w * C_ + c] = facc[c];
        }
        __syncthreads();
        if (tid < C_) {
            float s = bc[tid];
            #pragma unroll
            for (int w = 0; w < 6; w++) s += sred[w * C_ + tid];
            g_all[(size_t)row * C_ + tid] = s;
        }
        __syncthreads();
    }
}

// ---------------------------------------------------------------------------
__global__ void finalize_kernel(const int* __restrict__ nt, float* __restrict__ out,
                                int out_size)
{
    const int ALL = B_ * T_ * C_;
    const int FIN = B_ * C_;
    int i = blockIdx.x * blockDim.x + threadIdx.x;
    if (out_size >= ALL + FIN) {
        if (i < ALL) out[i] = g_all[i];
        if (i < FIN) {
            int b = i / C_, c = i - b * C_;
            int t = nt[b] - 1;
            out[ALL + i] = g_all[((size_t)(b * T_ + t)) * C_ + c];
        }
    } else if (out_size >= ALL) {
        if (i < ALL) out[i] = g_all[i];
    } else {
        if (i < FIN) {
            int b = i / C_, c = i - b * C_;
            int t = nt[b] - 1;
            out[i] = g_all[((size_t)(b * T_ + t)) * C_ + c];
        }
    }
}

// ---------------------------------------------------------------------------
extern "C" void kernel_launch(void* const* d_in, const int* in_sizes, int n_in,
                              void* d_out, int out_size)
{
    const float* H  = (const float*)d_in[0];
    const float* Wq = (const float*)d_in[1];
    const float* bq = (const float*)d_in[2];
    const float* Wk = (const float*)d_in[3];
    const float* bk = (const float*)d_in[4];
    const float* Wv = (const float*)d_in[5];
    const float* bv = (const float*)d_in[6];
    const float* Wo = (const float*)d_in[7];
    const float* bo = (const float*)d_in[8];
    const float* Wc = (const float*)d_in[9];
    const float* bc = (const float*)d_in[10];
    const int*   nt = (const int*)d_in[11];
    float* out = (float*)d_out;

    float *pq, *pk, *pv, *pctx, *pc;
    cudaGetSymbolAddress((void**)&pq,   g_q);
    cudaGetSymbolAddress((void**)&pk,   g_k);
    cudaGetSymbolAddress((void**)&pv,   g_v);
    cudaGetSymbolAddress((void**)&pctx, g_ctx);
    cudaGetSymbolAddress((void**)&pc,   g_c);

    static int smem_set = 0;
    if (!smem_set) {
        cudaFuncSetAttribute(tf32_gemm_bias,
                             cudaFuncAttributeMaxDynamicSharedMemorySize,
                             GEMM_SMEM_BYTES);
        smem_set = 1;
    }

    const int M = B_ * T_;

    // Fused QKV: one launch, gridDim.z = 3
    dim3 qkv_grid(D_ / GBN, M / GBM, 3);
    tf32_gemm_bias<<<qkv_grid, 256, GEMM_SMEM_BYTES>>>(
        H, Wq, bq, pq, Wk, bk, pk, Wv, bv, pv, M, D_, D_);

    attn_kernel<<<dim3(NH_, B_), 256>>>(nt);

    dim3 o_grid(D_ / GBN, M / GBM, 1);
    tf32_gemm_bias<<<o_grid, 256, GEMM_SMEM_BYTES>>>(
        pctx, Wo, bo, pc, Wo, bo, pc, Wo, bo, pc, M, D_, D_);

    classifier_kernel<<<M / CL_ROWS, CL_THREADS>>>(H, Wc, bc);

    const int ALL = B_ * T_ * C_;
    finalize_kernel<<<(ALL + 255) / 256, 256>>>(nt, out, out_size);
}

// round 5
// speedup vs baseline: 3.2254x; 1.1319x over previous
#include <cuda_runtime.h>
#include <cuda_fp16.h>
#include <cstdint>

#define B_ 64
#define T_ 256
#define D_ 768
#define NH_ 12
#define C_ 7
#define DH_ 64

// Scratch (device globals — no allocation allowed)
__device__ float  g_q[B_ * T_ * D_];
__device__ float  g_k[B_ * T_ * D_];
__device__ float  g_v[B_ * T_ * D_];
__device__ float  g_c[B_ * T_ * D_];
__device__ float  g_all[B_ * T_ * C_];
__device__ __half g_h16[B_ * T_ * D_];     // H in half
__device__ __half g_ctx16[B_ * T_ * D_];   // attention output in half
__device__ __half g_wt16[4 * D_ * D_];     // Wq^T,Wk^T,Wv^T,Wo^T (K-major, half)

// ---------------------------------------------------------------------------
__device__ __forceinline__ uint32_t smem_u32(const void* p) {
    uint32_t a;
    asm("{ .reg .u64 t; cvta.to.shared.u64 t, %1; cvt.u32.u64 %0, t; }" : "=r"(a) : "l"(p));
    return a;
}
__device__ __forceinline__ void cp_async16(uint32_t saddr, const void* src) {
    asm volatile("cp.async.cg.shared.global [%0], [%1], 16;" :: "r"(saddr), "l"(src) : "memory");
}
__device__ __forceinline__ void cp_commit() { asm volatile("cp.async.commit_group;" ::: "memory"); }
__device__ __forceinline__ void cp_wait0()  { asm volatile("cp.async.wait_group 0;" ::: "memory"); }
__device__ __forceinline__ void cp_wait1()  { asm volatile("cp.async.wait_group 1;" ::: "memory"); }

__device__ __forceinline__ void mma_f16(float c[4], const uint32_t a[4], const uint32_t b[2]) {
    asm volatile(
        "mma.sync.aligned.m16n8k16.row.col.f32.f16.f16.f32 "
        "{%0,%1,%2,%3},{%4,%5,%6,%7},{%8,%9},{%0,%1,%2,%3};"
        : "+f"(c[0]), "+f"(c[1]), "+f"(c[2]), "+f"(c[3])
        : "r"(a[0]), "r"(a[1]), "r"(a[2]), "r"(a[3]), "r"(b[0]), "r"(b[1]));
}

// ---------------------------------------------------------------------------
// Conversions
// ---------------------------------------------------------------------------
__global__ void conv_f2h(const float4* __restrict__ src, __half2* __restrict__ dst, int n4)
{
    int i = blockIdx.x * blockDim.x + threadIdx.x;
    if (i < n4) {
        float4 v = src[i];
        dst[2 * i]     = __floats2half2_rn(v.x, v.y);
        dst[2 * i + 1] = __floats2half2_rn(v.z, v.w);
    }
}

// g_wt16[z][n][k] = (half) W_z[k][n]
__global__ void transpose4(const float* __restrict__ Wq, const float* __restrict__ Wk,
                           const float* __restrict__ Wv, const float* __restrict__ Wo)
{
    __shared__ float t[32][33];
    const float* src = (blockIdx.z == 0) ? Wq : (blockIdx.z == 1) ? Wk :
                       (blockIdx.z == 2) ? Wv : Wo;
    __half* dst = g_wt16 + (size_t)blockIdx.z * D_ * D_;
    int x = blockIdx.x * 32 + threadIdx.x;
    int y = blockIdx.y * 32 + threadIdx.y;
    #pragma unroll
    for (int i = 0; i < 32; i += 8)
        t[threadIdx.y + i][threadIdx.x] = src[(size_t)(y + i) * D_ + x];
    __syncthreads();
    x = blockIdx.y * 32 + threadIdx.x;
    y = blockIdx.x * 32 + threadIdx.y;
    #pragma unroll
    for (int i = 0; i < 32; i += 8)
        dst[(size_t)(y + i) * D_ + x] = __float2half(t[threadIdx.x][threadIdx.y + i]);
}

// ---------------------------------------------------------------------------
// FP16 tensor-core GEMM: Out[M,N] = A[M,K] @ WT[N,K]^T + bias[N]   (fp32 accum)
// 128x128 tile, BK=32 halves, 256 threads (8 warps 4x2), warp tile 32x64.
// m16n8k16; 2-stage cp.async. blockIdx.z picks (bias,out); WT indexed by z.
// ---------------------------------------------------------------------------
#define HST 40                          // smem row stride in halves (80 B)
#define HSTAGE (128 * HST * 2 * 2)      // A(128 rows)+B(128 rows), bytes = 20480
#define HBK 32
#define HKT (D_ / HBK)                  // 24

__global__ __launch_bounds__(256, 2) void f16_gemm_bias(
    const __half* __restrict__ A, const __half* __restrict__ WTbase,
    const float* __restrict__ b0, float* __restrict__ O0,
    const float* __restrict__ b1, float* __restrict__ O1,
    const float* __restrict__ b2, float* __restrict__ O2)
{
    __shared__ __align__(16) char gsm[2 * HSTAGE];
    const uint32_t sbase = smem_u32(gsm);

    const int tid = threadIdx.x;
    const int bx = blockIdx.x, by = blockIdx.y, bz = blockIdx.z;

    const __half* W    = WTbase + (size_t)bz * D_ * D_;
    const float*  bias = (bz == 0) ? b0 : (bz == 1) ? b1 : b2;
    float*        Cout = (bz == 0) ? O0 : (bz == 1) ? O1 : O2;

    const int warp = tid >> 5;
    const int lane = tid & 31;
    const int gid = lane >> 2;        // 0..7
    const int tig = lane & 3;         // 0..3
    const int m0 = (warp & 3) * 32;
    const int n0 = (warp >> 2) * 64;

    const __half* Ag = A + (size_t)(by * 128) * D_;
    const __half* Wg = W + (size_t)(bx * 128) * D_;

    const int frow = tid >> 1;          // 0..127
    const int g0   = (tid & 1) * 2;     // granule base (16B granules)

    float acc[2][8][4] = {};

    // fill stage buf with K-chunk kt
    #define HFILL(buf, kt) do {                                                   \
        const uint32_t sa = sbase + (buf) * HSTAGE;                               \
        const uint32_t sb = sa + 128 * HST * 2;                                   \
        const int kb = (kt) * HBK;                                                \
        _Pragma("unroll")                                                         \
        for (int g = g0; g < g0 + 2; g++) {                                       \
            cp_async16(sa + frow * (HST * 2) + g * 16,                            \
                       Ag + (size_t)frow * D_ + kb + g * 8);                      \
            cp_async16(sb + frow * (HST * 2) + g * 16,                            \
                       Wg + (size_t)frow * D_ + kb + g * 8);                      \
        }                                                                         \
    } while (0)

    HFILL(0, 0);
    cp_commit();

    for (int kt = 0; kt < HKT; kt++) {
        const int buf = kt & 1;
        if (kt + 1 < HKT) HFILL(buf ^ 1, kt + 1);
        cp_commit();
        cp_wait1();
        __syncthreads();

        const __half* sA = (const __half*)(gsm + buf * HSTAGE);
        const __half* sB = sA + 128 * HST;

        #pragma unroll
        for (int kk = 0; kk < HBK; kk += 16) {
            uint32_t a[2][4], b[8][2];
            #pragma unroll
            for (int mt = 0; mt < 2; mt++) {
                int mr = m0 + mt * 16 + gid;
                a[mt][0] = *(const uint32_t*)&sA[mr * HST + kk + 2 * tig];
                a[mt][1] = *(const uint32_t*)&sA[(mr + 8) * HST + kk + 2 * tig];
                a[mt][2] = *(const uint32_t*)&sA[mr * HST + kk + 2 * tig + 8];
                a[mt][3] = *(const uint32_t*)&sA[(mr + 8) * HST + kk + 2 * tig + 8];
            }
            #pragma unroll
            for (int nt = 0; nt < 8; nt++) {
                int nc = n0 + nt * 8 + gid;
                b[nt][0] = *(const uint32_t*)&sB[nc * HST + kk + 2 * tig];
                b[nt][1] = *(const uint32_t*)&sB[nc * HST + kk + 2 * tig + 8];
            }
            #pragma unroll
            for (int mt = 0; mt < 2; mt++)
                #pragma unroll
                for (int nt = 0; nt < 8; nt++)
                    mma_f16(acc[mt][nt], a[mt], b[nt]);
        }
        __syncthreads();
    }
    cp_wait0();

    #pragma unroll
    for (int mt = 0; mt < 2; mt++) {
        #pragma unroll
        for (int nt = 0; nt < 8; nt++) {
            int row = by * 128 + m0 + mt * 16 + gid;
            int col = bx * 128 + n0 + nt * 8 + tig * 2;
            float bx0 = bias[col], bx1 = bias[col + 1];
            float2 o0 = {acc[mt][nt][0] + bx0, acc[mt][nt][1] + bx1};
            float2 o1 = {acc[mt][nt][2] + bx0, acc[mt][nt][3] + bx1};
            *(float2*)(Cout + (size_t)row * D_ + col) = o0;
            *(float2*)(Cout + (size_t)(row + 8) * D_ + col) = o1;
        }
    }
}

// ---------------------------------------------------------------------------
// Attention: one block per (head, batch); one thread per query. Online softmax.
// Writes ctx as half (out-proj A operand).
// ---------------------------------------------------------------------------
__global__ __launch_bounds__(256) void attn_kernel(const int* __restrict__ num_turns)
{
    const int h = blockIdx.x;
    const int b = blockIdx.y;
    const int q = threadIdx.x;

    __shared__ float Ks[64][64];
    __shared__ float Vs[64][64];

    const int nt = num_turns[b];
    const int limit = (q < nt) ? q : nt;
    const int maxkeys = (T_ - 1 < nt) ? (T_ - 1) : nt;
    const int nchunks = (maxkeys + 63) >> 6;

    const float* qptr = g_q + ((size_t)(b * T_ + q)) * D_ + h * DH_;
    float qr[64];
    #pragma unroll
    for (int d = 0; d < 64; d += 4) {
        float4 v = *(const float4*)(qptr + d);
        qr[d] = v.x; qr[d + 1] = v.y; qr[d + 2] = v.z; qr[d + 3] = v.w;
    }

    float m = -1e30f, l = 0.f;
    float acc[64] = {};
    const float scale = 0.125f;

    for (int ch = 0; ch < nchunks; ch++) {
        const int kbase = ch * 64;
        {
            int r  = threadIdx.x >> 2;
            int c0 = (threadIdx.x & 3) * 16;
            const float* kp = g_k + ((size_t)(b * T_ + kbase + r)) * D_ + h * DH_ + c0;
            const float* vp = g_v + ((size_t)(b * T_ + kbase + r)) * D_ + h * DH_ + c0;
            #pragma unroll
            for (int j = 0; j < 16; j += 4) {
                *(float4*)(&Ks[r][c0 + j]) = *(const float4*)(kp + j);
                *(float4*)(&Vs[r][c0 + j]) = *(const float4*)(vp + j);
            }
        }
        __syncthreads();

        const int kend = (64 < limit - kbase) ? 64 : (limit - kbase);
        for (int kk = 0; kk < kend; kk++) {
            const float4* kr = (const float4*)(&Ks[kk][0]);
            float s0 = 0.f, s1 = 0.f, s2 = 0.f, s3 = 0.f;
            #pragma unroll
            for (int i = 0; i < 16; i++) {
                float4 kv = kr[i];
                s0 = fmaf(qr[4 * i    ], kv.x, s0);
                s1 = fmaf(qr[4 * i + 1], kv.y, s1);
                s2 = fmaf(qr[4 * i + 2], kv.z, s2);
                s3 = fmaf(qr[4 * i + 3], kv.w, s3);
            }
            float s = ((s0 + s1) + (s2 + s3)) * scale;
            const float4* vr = (const float4*)(&Vs[kk][0]);
            if (s > m) {
                float corr = __expf(m - s);
                m = s;
                l = l * corr + 1.f;
                #pragma unroll
                for (int i = 0; i < 16; i++) {
                    float4 vv = vr[i];
                    acc[4 * i    ] = acc[4 * i    ] * corr + vv.x;
                    acc[4 * i + 1] = acc[4 * i + 1] * corr + vv.y;
                    acc[4 * i + 2] = acc[4 * i + 2] * corr + vv.z;
                    acc[4 * i + 3] = acc[4 * i + 3] * corr + vv.w;
                }
            } else {
                float p = __expf(s - m);
                l += p;
                #pragma unroll
                for (int i = 0; i < 16; i++) {
                    float4 vv = vr[i];
                    acc[4 * i    ] = fmaf(p, vv.x, acc[4 * i    ]);
                    acc[4 * i + 1] = fmaf(p, vv.y, acc[4 * i + 1]);
                    acc[4 * i + 2] = fmaf(p, vv.z, acc[4 * i + 2]);
                    acc[4 * i + 3] = fmaf(p, vv.w, acc[4 * i + 3]);
                }
            }
        }
        __syncthreads();
    }

    __half2* op = (__half2*)(g_ctx16 + ((size_t)(b * T_ + q)) * D_ + h * DH_);
    if (limit > 0) {
        float invl = 1.f / l;
        #pragma unroll
        for (int d = 0; d < 64; d += 2)
            op[d >> 1] = __floats2half2_rn(acc[d] * invl, acc[d + 1] * invl);
    } else {
        __half2 z = __floats2half2_rn(0.f, 0.f);
        #pragma unroll
        for (int d = 0; d < 64; d += 2) op[d >> 1] = z;
    }
}

// ---------------------------------------------------------------------------
// Classifier
// ---------------------------------------------------------------------------
#define CL_ROWS 16
#define CL_THREADS 192

__global__ __launch_bounds__(CL_THREADS) void classifier_kernel(
    const float* __restrict__ H, const float* __restrict__ Wc,
    const float* __restrict__ bc)
{
    __shared__ float sWc[2 * D_ * C_];
    __shared__ float sred[6 * C_];

    const int tid = threadIdx.x;
    for (int i = tid; i < 2 * D_ * C_; i += CL_THREADS) sWc[i] = Wc[i];
    __syncthreads();

    const int d0 = tid * 4;
    const int row0 = blockIdx.x * CL_ROWS;

    for (int r = 0; r < CL_ROWS; r++) {
        const int row = row0 + r;
        const int t = row & (T_ - 1);
        float facc[C_] = {};
        {
            float4 hv = *(const float4*)(H + (size_t)row * D_ + d0);
            #pragma unroll
            for (int c = 0; c < C_; c++) {
                facc[c] = fmaf(hv.x, sWc[(d0    ) * C_ + c], facc[c]);
                facc[c] = fmaf(hv.y, sWc[(d0 + 1) * C_ + c], facc[c]);
                facc[c] = fmaf(hv.z, sWc[(d0 + 2) * C_ + c], facc[c]);
                facc[c] = fmaf(hv.w, sWc[(d0 + 3) * C_ + c], facc[c]);
            }
            if (t > 0) {
                float4 cv = *(const float4*)(g_c + (size_t)row * D_ + d0);
                #pragma unroll
                for (int c = 0; c < C_; c++) {
                    facc[c] = fmaf(cv.x, sWc[(D_ + d0    ) * C_ + c], facc[c]);
                    facc[c] = fmaf(cv.y, sWc[(D_ + d0 + 1) * C_ + c], facc[c]);
                    facc[c] = fmaf(cv.z, sWc[(D_ + d0 + 2) * C_ + c], facc[c]);
                    facc[c] = fmaf(cv.w, sWc[(D_ + d0 + 3) * C_ + c], facc[c]);
                }
            }
        }
        #pragma unroll
        for (int c = 0; c < C_; c++)
            #pragma unroll
            for (int off = 16; off; off >>= 1)
                facc[c] += __shfl_down_sync(0xffffffff, facc[c], off);
        if ((tid & 31) == 0) {
            int w = tid >> 5;
            #pragma unroll
            for (int c = 0; c < C_; c++) sred[w * C_ + c] = facc[c];
        }
        __syncthreads();
        if (tid < C_) {
            float s = bc[tid];
            #pragma unroll
            for (int w = 0; w < 6; w++) s += sred[w * C_ + tid];
            g_all[(size_t)row * C_ + tid] = s;
        }
        __syncthreads();
    }
}

// ---------------------------------------------------------------------------
__global__ void finalize_kernel(const int* __restrict__ nt, float* __restrict__ out,
                                int out_size)
{
    const int ALL = B_ * T_ * C_;
    const int FIN = B_ * C_;
    int i = blockIdx.x * blockDim.x + threadIdx.x;
    if (out_size >= ALL + FIN) {
        if (i < ALL) out[i] = g_all[i];
        if (i < FIN) {
            int b = i / C_, c = i - b * C_;
            int t = nt[b] - 1;
            out[ALL + i] = g_all[((size_t)(b * T_ + t)) * C_ + c];
        }
    } else if (out_size >= ALL) {
        if (i < ALL) out[i] = g_all[i];
    } else {
        if (i < FIN) {
            int b = i / C_, c = i - b * C_;
            int t = nt[b] - 1;
            out[i] = g_all[((size_t)(b * T_ + t)) * C_ + c];
        }
    }
}

// ---------------------------------------------------------------------------
extern "C" void kernel_launch(void* const* d_in, const int* in_sizes, int n_in,
                              void* d_out, int out_size)
{
    const float* H  = (const float*)d_in[0];
    const float* Wq = (const float*)d_in[1];
    const float* bq = (const float*)d_in[2];
    const float* Wk = (const float*)d_in[3];
    const float* bk = (const float*)d_in[4];
    const float* Wv = (const float*)d_in[5];
    const float* bv = (const float*)d_in[6];
    const float* Wo = (const float*)d_in[7];
    const float* bo = (const float*)d_in[8];
    const float* Wc = (const float*)d_in[9];
    const float* bc = (const float*)d_in[10];
    const int*   nt = (const int*)d_in[11];
    float* out = (float*)d_out;

    float *pq, *pk, *pv, *pc;
    __half *ph16, *pctx16, *pwt16;
    cudaGetSymbolAddress((void**)&pq,     g_q);
    cudaGetSymbolAddress((void**)&pk,     g_k);
    cudaGetSymbolAddress((void**)&pv,     g_v);
    cudaGetSymbolAddress((void**)&pc,     g_c);
    cudaGetSymbolAddress((void**)&ph16,   g_h16);
    cudaGetSymbolAddress((void**)&pctx16, g_ctx16);
    cudaGetSymbolAddress((void**)&pwt16,  g_wt16);

    const int M = B_ * T_;

    // 0) conversions
    const int n4 = M * D_ / 4;
    conv_f2h<<<(n4 + 255) / 256, 256>>>((const float4*)H, (__half2*)ph16, n4);
    transpose4<<<dim3(D_ / 32, D_ / 32, 4), dim3(32, 8)>>>(Wq, Wk, Wv, Wo);

    // 1) fused QKV (z = 0,1,2)
    dim3 qkv_grid(D_ / 128, M / 128, 3);
    f16_gemm_bias<<<qkv_grid, 256>>>(ph16, pwt16, bq, pq, bk, pk, bv, pv);

    // 2) attention
    attn_kernel<<<dim3(NH_, B_), 256>>>(nt);

    // 3) out-proj (Wo^T at slot 3)
    dim3 o_grid(D_ / 128, M / 128, 1);
    f16_gemm_bias<<<o_grid, 256>>>(pctx16, pwt16 + (size_t)3 * D_ * D_, bo, pc, bo, pc, bo, pc);

    // 4) classifier + 5) finalize
    classifier_kernel<<<M / CL_ROWS, CL_THREADS>>>(H, Wc, bc);

    const int ALL = B_ * T_ * C_;
    finalize_kernel<<<(ALL + 255) / 256, 256>>>(nt, out, out_size);
}